// round 14
// baseline (speedup 1.0000x reference)
#include <cuda_runtime.h>
#include <stdint.h>

#define ROW_N 2048
#define K_SEL 1024
#define NT    256
#define CAP   64
#define FULLM 0xFFFFFFFFu

__device__ __forceinline__ uint32_t f2u_ord(float x) {
    uint32_t b = __float_as_uint(x);
    uint32_t m = (uint32_t)(((int32_t)b) >> 31) | 0x80000000u;
    return b ^ m;
}
__device__ __forceinline__ float u2f_ord(uint32_t u) {
    uint32_t m = (uint32_t)(((int32_t)(~u)) >> 31) | 0x80000000u;
    return __uint_as_float(u ^ m);
}
__device__ __forceinline__ int bin_of(float v, int lvl, float scale) {
    return (lvl < 2) ? __float2int_rd(fmaf(v, scale, 128.0f))
                     : (int)(f2u_ord(v) >> 24);
}
__device__ __forceinline__ void cp_async16(uint32_t saddr, const void* gptr) {
    asm volatile("cp.async.cg.shared.global [%0], [%1], 16;" :: "r"(saddr), "l"(gptr));
}

__global__ __launch_bounds__(NT, 8) void kta_kernel(const float* __restrict__ in,
                                                    float* __restrict__ out) {
    __shared__ float    s_row[2][ROW_N];      // 16 KB
    __shared__ uint32_t s_hist[512];          // 2 KB
    __shared__ float    s_cand[2][CAP];
    __shared__ uint32_t s_w[2][8];
    __shared__ uint32_t s_selbin[2], s_selrem[2];
    __shared__ uint32_t s_cnt[2];
    __shared__ float    s_T[2];
    __shared__ uint32_t s_minu, s_c;

    const int t    = threadIdx.x;
    const int lane = t & 31;
    const int wid  = t >> 5;
    const size_t baseA = (size_t)blockIdx.x * (2 * ROW_N);

    // ---- async-copy both rows into SMEM (4 x LDGSTS.16 per thread) ----
    {
        const float* gA = in + baseA + t * 8;
        const float* gB = in + baseA + ROW_N + t * 8;
        uint32_t sA = (uint32_t)__cvta_generic_to_shared(&s_row[0][t * 8]);
        uint32_t sB = (uint32_t)__cvta_generic_to_shared(&s_row[1][t * 8]);
        cp_async16(sA,      gA);
        cp_async16(sA + 16, gA + 4);
        cp_async16(sB,      gB);
        cp_async16(sB + 16, gB + 4);
        asm volatile("cp.async.commit_group;");
    }
    if (t == 0) { s_cnt[0] = 0; s_cnt[1] = 0; }
    asm volatile("cp.async.wait_group 0;" ::: "memory");
    __syncthreads();

    bool gotA = false, gotB = false;
    int  lvlA = 0, lvlB = 0;

    for (int lvl = 0; lvl < 3; lvl++) {
        const float scale = (lvl == 0) ? 1280.0f : (256.0f / 1.2f);

        s_hist[t] = 0; s_hist[t + 256] = 0;
        if (t == 0) {
            if (!gotA) s_selbin[0] = FULLM;
            if (!gotB) s_selbin[1] = FULLM;
        }
        __syncthreads();

        if (!gotA) {
            float4 v0 = *(const float4*)&s_row[0][t * 8];
            float4 v1 = *(const float4*)&s_row[0][t * 8 + 4];
            float v[8] = {v0.x,v0.y,v0.z,v0.w, v1.x,v1.y,v1.z,v1.w};
            uint32_t clo = 0;
#pragma unroll
            for (int e = 0; e < 8; e++) {
                int b = bin_of(v[e], lvl, scale);
                clo += ((uint32_t)b >> 31);
                if ((unsigned)b < 256u) atomicAdd(&s_hist[b], 1u);
            }
            clo = __reduce_add_sync(FULLM, clo);
            if (lane == 0) s_w[0][wid] = clo;
        }
        if (!gotB) {
            float4 v0 = *(const float4*)&s_row[1][t * 8];
            float4 v1 = *(const float4*)&s_row[1][t * 8 + 4];
            float v[8] = {v0.x,v0.y,v0.z,v0.w, v1.x,v1.y,v1.z,v1.w};
            uint32_t clo = 0;
#pragma unroll
            for (int e = 0; e < 8; e++) {
                int b = bin_of(v[e], lvl, scale);
                clo += ((uint32_t)b >> 31);
                if ((unsigned)b < 256u) atomicAdd(&s_hist[256 + b], 1u);
            }
            clo = __reduce_add_sync(FULLM, clo);
            if (lane == 0) s_w[1][wid] = clo;
        }
        __syncthreads();

        if (wid < 2) {
            const int r = wid;
            const bool need = (r == 0) ? !gotA : !gotB;
            if (need) {
                uint32_t x = (lane < 8) ? s_w[r][lane] : 0u;
                const int clo = (int)__reduce_add_sync(FULLM, x);
                const int k2  = K_SEL - clo;

                const uint4* h4 = (const uint4*)(s_hist + r * 256);
                uint4 p = h4[lane * 2], q = h4[lane * 2 + 1];
                uint32_t c[8] = {p.x,p.y,p.z,p.w, q.x,q.y,q.z,q.w};
                uint32_t lt = c[0]+c[1]+c[2]+c[3]+c[4]+c[5]+c[6]+c[7];
                uint32_t inc = lt;
#pragma unroll
                for (int o = 1; o < 32; o <<= 1) {
                    uint32_t v = __shfl_up_sync(FULLM, inc, o);
                    if (lane >= o) inc += v;
                }
                int exc = (int)(inc - lt);
                if (exc < k2 && k2 <= (int)inc) {
                    int run = exc, fbn = -1;
#pragma unroll
                    for (int j = 0; j < 8; j++) {
                        if (fbn < 0 && run < k2 && k2 <= run + (int)c[j]) fbn = j;
                        else if (fbn < 0) run += (int)c[j];
                    }
                    s_selbin[r] = (uint32_t)(lane * 8 + fbn);
                    s_selrem[r] = (uint32_t)(k2 - run);
                }
            }
        }
        __syncthreads();

        bool pA = gotA, pB = gotB;
        gotA = (s_selbin[0] != FULLM);
        gotB = (s_selbin[1] != FULLM);
        if (!pA && gotA) lvlA = lvl;
        if (!pB && gotB) lvlB = lvl;
        if (gotA && gotB) break;
    }

    const int bselA = (int)s_selbin[0], bselB = (int)s_selbin[1];
    const float scA = (lvlA == 0) ? 1280.0f : (256.0f / 1.2f);
    const float scB = (lvlB == 0) ? 1280.0f : (256.0f / 1.2f);

    // ---- gather crossing-bin elements from SMEM (bit-identical bin math) ----
    {
        float4 v0 = *(const float4*)&s_row[0][t * 8];
        float4 v1 = *(const float4*)&s_row[0][t * 8 + 4];
        float v[8] = {v0.x,v0.y,v0.z,v0.w, v1.x,v1.y,v1.z,v1.w};
#pragma unroll
        for (int e = 0; e < 8; e++) {
            if (bin_of(v[e], lvlA, scA) == bselA) {
                uint32_t pos = atomicAdd(&s_cnt[0], 1u);
                if (pos < CAP) s_cand[0][pos] = v[e];
            }
        }
    }
    {
        float4 v0 = *(const float4*)&s_row[1][t * 8];
        float4 v1 = *(const float4*)&s_row[1][t * 8 + 4];
        float v[8] = {v0.x,v0.y,v0.z,v0.w, v1.x,v1.y,v1.z,v1.w};
#pragma unroll
        for (int e = 0; e < 8; e++) {
            if (bin_of(v[e], lvlB, scB) == bselB) {
                uint32_t pos = atomicAdd(&s_cnt[1], 1u);
                if (pos < CAP) s_cand[1][pos] = v[e];
            }
        }
    }
    __syncthreads();

    // ---- per-row threshold ----
#pragma unroll
    for (int r = 0; r < 2; r++) {
        const int   B    = (int)s_cnt[r];
        int         rem  = (int)s_selrem[r];
        const int   bsel = (r == 0) ? bselA : bselB;
        const int   lvlR = (r == 0) ? lvlA  : lvlB;
        const float scR  = (r == 0) ? scA   : scB;

        if (B <= CAP) {
            if (t < B) {
                float v = s_cand[r][t];
                int less = 0, leq = 0;
                for (int j = 0; j < B; j++) {
                    float c = s_cand[r][j];
                    less += (c <  v) ? 1 : 0;
                    leq  += (c <= v) ? 1 : 0;
                }
                if (less < rem && rem <= leq) s_T[r] = v;
            }
        } else {
            // rare overflow: min-extraction over SMEM row (exact, bounded)
            uint32_t curnext = 0;
            while (true) {
                if (t == 0) { s_minu = FULLM; s_c = 0; }
                __syncthreads();
                for (int i = t; i < ROW_N; i += NT) {
                    float v = s_row[r][i];
                    uint32_t u = f2u_ord(v);
                    if (bin_of(v, lvlR, scR) == bsel && u >= curnext)
                        atomicMin(&s_minu, u);
                }
                __syncthreads();
                uint32_t m = s_minu;
                if (m == FULLM) { if (t == 0) s_T[r] = u2f_ord(curnext - 1u); __syncthreads(); break; }
                for (int i = t; i < ROW_N; i += NT)
                    if (f2u_ord(s_row[r][i]) == m) atomicAdd(&s_c, 1u);
                __syncthreads();
                uint32_t dup = s_c;
                if ((int)dup >= rem) { if (t == 0) s_T[r] = u2f_ord(m); __syncthreads(); break; }
                rem    -= (int)dup;
                curnext = m + 1u;
                __syncthreads();
            }
        }
    }
    __syncthreads();

    // ---- apply + store from SMEM ----
    {
        const float TA = s_T[0];
        float4 v0 = *(const float4*)&s_row[0][t * 8];
        float4 v1 = *(const float4*)&s_row[0][t * 8 + 4];
        float4 o0, o1;
        o0.x = (v0.x <= TA) ? 0.0f : v0.x;
        o0.y = (v0.y <= TA) ? 0.0f : v0.y;
        o0.z = (v0.z <= TA) ? 0.0f : v0.z;
        o0.w = (v0.w <= TA) ? 0.0f : v0.w;
        o1.x = (v1.x <= TA) ? 0.0f : v1.x;
        o1.y = (v1.y <= TA) ? 0.0f : v1.y;
        o1.z = (v1.z <= TA) ? 0.0f : v1.z;
        o1.w = (v1.w <= TA) ? 0.0f : v1.w;
        float4* oA = (float4*)(out + baseA + t * 8);
        oA[0] = o0; oA[1] = o1;
    }
    {
        const float TB = s_T[1];
        float4 v0 = *(const float4*)&s_row[1][t * 8];
        float4 v1 = *(const float4*)&s_row[1][t * 8 + 4];
        float4 o0, o1;
        o0.x = (v0.x <= TB) ? 0.0f : v0.x;
        o0.y = (v0.y <= TB) ? 0.0f : v0.y;
        o0.z = (v0.z <= TB) ? 0.0f : v0.z;
        o0.w = (v0.w <= TB) ? 0.0f : v0.w;
        o1.x = (v1.x <= TB) ? 0.0f : v1.x;
        o1.y = (v1.y <= TB) ? 0.0f : v1.y;
        o1.z = (v1.z <= TB) ? 0.0f : v1.z;
        o1.w = (v1.w <= TB) ? 0.0f : v1.w;
        float4* oB = (float4*)(out + baseA + ROW_N + t * 8);
        oB[0] = o0; oB[1] = o1;
    }
}

extern "C" void kernel_launch(void* const* d_in, const int* in_sizes, int n_in,
                              void* d_out, int out_size) {
    const float* in = (const float*)d_in[0];
    float* out = (float*)d_out;
    int pairs = in_sizes[0] / (2 * ROW_N);
    kta_kernel<<<pairs, NT>>>(in, out);
}